// round 6
// baseline (speedup 1.0000x reference)
#include <cuda_runtime.h>
#include <cstdint>

// ---------------------------------------------------------------------------
// CMAFM block, fully fused: one CTA per 8x8 window. 4096 CTAs, 128 threads.
// GEMMs: 8x8 per-thread micro-tile (full 64x128 output across 128 threads),
// k staged in 64-wide halves via cp.async, f32x2 packed FMA accumulation.
// 5 rotating data buffers + dedicated weight stage. Attention: 4 warps =
// 4 heads, 2 row passes, no-max softmax (scores ~0.05, shift-invariant).
// ---------------------------------------------------------------------------

#define TB 128
using u64 = unsigned long long;

constexpr int CC    = 128;
constexpr int HH    = 256;
constexpr int WWI   = 256;
constexpr int NPIX  = 64;
constexpr int XP    = 132;          // data buffer row pitch (floats)
constexpr int WPI   = 68;           // weight stage pitch (floats)
constexpr int BUF   = NPIX * XP;    // 8448 floats
constexpr int WSTF  = 128 * WPI;    // 8704 floats
constexpr int SMEM_FLOATS = 5 * BUF + WSTF;   // 50944 floats = 203776 B
constexpr size_t NTOT = 4ull * 128 * 256 * 256;

struct P {
    const float *F_opt, *F_sar;
    const float *wq_opt, *bq_opt, *wk_opt, *bk_opt, *wv_opt, *bv_opt;
    const float *wq_sar, *bq_sar, *wk_sar, *bk_sar, *wv_sar, *bv_sar;
    const float *pw_o2s, *pb_o2s, *pw_s2o, *pb_s2o;
    const float *gow, *gob, *gsw, *gsb;
    const float *fw, *fb;
    const float *gma, *bta, *mu, *var;
    float *out;
};

// ---- f32x2 helpers --------------------------------------------------------
__device__ __forceinline__ void f2fma(u64& d, u64 a, u64 b) {
    asm("fma.rn.f32x2 %0, %1, %2, %0;" : "+l"(d) : "l"(a), "l"(b));
}
__device__ __forceinline__ u64 f2mul(u64 a, u64 b) {
    u64 d; asm("mul.rn.f32x2 %0, %1, %2;" : "=l"(d) : "l"(a), "l"(b)); return d;
}
__device__ __forceinline__ u64 f2add(u64 a, u64 b) {
    u64 d; asm("add.rn.f32x2 %0, %1, %2;" : "=l"(d) : "l"(a), "l"(b)); return d;
}
__device__ __forceinline__ u64 dup2(float v) {
    u64 d; asm("mov.b64 %0, {%1, %1};" : "=l"(d) : "f"(v)); return d;
}
__device__ __forceinline__ float f2sum(u64 a) {
    float lo, hi; asm("mov.b64 {%0, %1}, %2;" : "=f"(lo), "=f"(hi) : "l"(a));
    return lo + hi;
}
__device__ __forceinline__ void cp16(uint32_t s, const float* g) {
    asm volatile("cp.async.cg.shared.global [%0], [%1], 16;" :: "r"(s), "l"(g));
}

// Load one window (64 px x 128 ch) from NCHW global into smem [n][c].
// 128 threads: thread = channel.
__device__ __forceinline__ void load_window(float* dst, const float* __restrict__ src,
                                            int gbase, int tid) {
    const float* s = src + gbase + tid * (HH * WWI);
#pragma unroll
    for (int i = 0; i < 8; ++i) {
        float4 a = *(const float4*)(s + i * WWI);
        float4 b = *(const float4*)(s + i * WWI + 4);
        float* d = dst + (i * 8) * XP + tid;
        d[0]      = a.x; d[XP]     = a.y; d[2 * XP] = a.z; d[3 * XP] = a.w;
        d[4 * XP] = b.x; d[5 * XP] = b.y; d[6 * XP] = b.z; d[7 * XP] = b.w;
    }
}

// Transposed store: smem [n][c] -> NCHW global.
__device__ __forceinline__ void store_window(float* __restrict__ g, const float* sbuf,
                                             int gbase, int tid) {
    float* gp = g + gbase + tid * (HH * WWI);
#pragma unroll
    for (int i = 0; i < 8; ++i) {
        const float* sp = sbuf + (i * 8) * XP + tid;
        *(float4*)(gp + i * WWI) =
            make_float4(sp[0], sp[XP], sp[2 * XP], sp[3 * XP]);
        *(float4*)(gp + i * WWI + 4) =
            make_float4(sp[4 * XP], sp[5 * XP], sp[6 * XP], sp[7 * XP]);
    }
}

// ---------------------------------------------------------------------------
// out[64][128] = [x0 | x1][64][CIN] @ W^T + bias.  W row-major [128][CIN].
// 8x8 per-thread tile: rows rg+8i, cols cg+16j. k in 64-wide halves staged
// via cp.async. In-place (outb==x0) is safe.
// ---------------------------------------------------------------------------
__device__ __noinline__ void gemm_core(const float* __restrict__ Wg, int CIN,
                                       const float* __restrict__ bias,
                                       const float* __restrict__ x0,
                                       const float* __restrict__ x1,
                                       float* __restrict__ outb,
                                       float* __restrict__ wst) {
    const int tid = threadIdx.x;
    const int L = tid & 31, w = tid >> 5;
    const int rg = L & 7;                        // 0..7
    const int cg = (L >> 3) | (w << 2);          // 0..15
    const int nh = CIN >> 6;
    const uint32_t wst_s = (uint32_t)__cvta_generic_to_shared(wst);

    u64 acc[8][8];
#pragma unroll
    for (int i = 0; i < 8; ++i)
#pragma unroll
        for (int j = 0; j < 8; ++j) acc[i][j] = 0ull;

    for (int h = 0; h < nh; ++h) {
        __syncthreads();  // wst free, prior outputs/readers settled
        {
            const float* Wh = Wg + h * 64;
#pragma unroll
            for (int it = 0; it < 16; ++it) {
                const int idx = tid * 4 + it * (TB * 4);
                const int r = idx >> 6, k = idx & 63;
                cp16(wst_s + (r * WPI + k) * 4, Wh + r * CIN + k);
            }
            asm volatile("cp.async.commit_group;");
            asm volatile("cp.async.wait_group 0;");
        }
        __syncthreads();

        const float* xs = ((h >= 2) ? x1 : x0) + (h & 1) * 64 + rg * XP;
        const float* wr = wst + cg * WPI;
#pragma unroll 2
        for (int ci = 0; ci < 64; ci += 4) {
            ulonglong2 xa[8];
#pragma unroll
            for (int i = 0; i < 8; ++i)
                xa[i] = *(const ulonglong2*)(xs + i * 8 * XP + ci);
#pragma unroll
            for (int j = 0; j < 8; ++j) {
                ulonglong2 wb = *(const ulonglong2*)(wr + j * 16 * WPI + ci);
#pragma unroll
                for (int i = 0; i < 8; ++i) {
                    f2fma(acc[i][j], xa[i].x, wb.x);
                    f2fma(acc[i][j], xa[i].y, wb.y);
                }
            }
        }
    }
    __syncthreads();  // all reads of x done before (possibly in-place) writes
#pragma unroll
    for (int j = 0; j < 8; ++j) {
        const int cc = cg + 16 * j;
        const float b = __ldg(bias + cc);
#pragma unroll
        for (int i = 0; i < 8; ++i)
            outb[(rg + 8 * i) * XP + cc] = f2sum(acc[i][j]) + b;
    }
    __syncthreads();
}

// ---------------------------------------------------------------------------
// Window attention: 4 warps = 4 heads; 2 passes of 32 rows, lane owns a row.
// head_dim=32 = 16 packed f32x2. No-max softmax (scores tiny, shift-inv).
// Ob may alias Qb: each warp touches only its head's 32 columns, and within
// a pass the row it writes was read by itself only -> no cross-warp hazard.
// ---------------------------------------------------------------------------
__device__ __forceinline__ void attention(const float* __restrict__ Qb,
                                          const float* __restrict__ Kb,
                                          const float* __restrict__ Vb,
                                          float* __restrict__ Ob, int tid) {
    const int L = tid & 31, head = tid >> 5;
    const float* kbase = Kb + head * 32;
    const float* vbase = Vb + head * 32;

#pragma unroll
    for (int pass = 0; pass < 2; ++pass) {
        const int row = pass * 32 + L;
        u64 q[16];
        {
            const ulonglong2* qp = (const ulonglong2*)(Qb + row * XP + head * 32);
            const u64 sc2 = dup2(0.17677669529663687f);  // 32^-0.5
#pragma unroll
            for (int t = 0; t < 8; ++t) {
                ulonglong2 v = qp[t];
                q[2 * t]     = f2mul(v.x, sc2);
                q[2 * t + 1] = f2mul(v.y, sc2);
            }
        }
        float l = 0.f;
        u64 o[16];
#pragma unroll
        for (int t = 0; t < 16; ++t) o[t] = 0ull;

        for (int j = 0; j < 64; ++j) {
            const ulonglong2* kp = (const ulonglong2*)(kbase + j * XP);
            u64 d0 = 0ull, d1 = 0ull, d2 = 0ull, d3 = 0ull;
#pragma unroll
            for (int t = 0; t < 4; ++t) {
                ulonglong2 ka = kp[2 * t], kb = kp[2 * t + 1];
                f2fma(d0, q[4 * t],     ka.x);
                f2fma(d1, q[4 * t + 1], ka.y);
                f2fma(d2, q[4 * t + 2], kb.x);
                f2fma(d3, q[4 * t + 3], kb.y);
            }
            const float e = __expf(f2sum(f2add(f2add(d0, d1), f2add(d2, d3))));
            l += e;
            const u64 ee = dup2(e);
            const ulonglong2* vp = (const ulonglong2*)(vbase + j * XP);
#pragma unroll
            for (int t = 0; t < 8; ++t) {
                ulonglong2 v2 = vp[t];
                f2fma(o[2 * t],     ee, v2.x);
                f2fma(o[2 * t + 1], ee, v2.y);
            }
        }
        const u64 inv2 = dup2(1.f / l);
        ulonglong2* op = (ulonglong2*)(Ob + row * XP + head * 32);
#pragma unroll
        for (int t = 0; t < 8; ++t) {
            ulonglong2 r;
            r.x = f2mul(o[2 * t], inv2);
            r.y = f2mul(o[2 * t + 1], inv2);
            op[t] = r;
        }
    }
    __syncthreads();
}

__device__ __forceinline__ float sigmoidf_(float x) {
    return 1.f / (1.f + __expf(-x));
}

extern __shared__ float smem[];

__global__ void __launch_bounds__(TB, 1) cmafm_kernel(P p) {
    float* B0 = smem;
    float* B1 = smem + BUF;
    float* B2 = smem + 2 * BUF;
    float* B3 = smem + 3 * BUF;
    float* B4 = smem + 4 * BUF;
    float* WST = smem + 5 * BUF;

    const int tid  = threadIdx.x;
    const int widx = blockIdx.x;
    const int b  = widx >> 10;
    const int wh = (widx >> 5) & 31;
    const int ww = widx & 31;
    const int gbase = b * (CC * HH * WWI) + (wh * 8) * WWI + ww * 8;

    load_window(B0, p.F_opt, gbase, tid);
    load_window(B1, p.F_sar, gbase, tid);

    // --- direction opt->sar ---
    gemm_core(p.wq_opt, 128, p.bq_opt, B0, nullptr, B2, WST);   // Qo
    gemm_core(p.wk_sar, 128, p.bk_sar, B1, nullptr, B3, WST);   // Ks
    gemm_core(p.wv_sar, 128, p.bv_sar, B1, nullptr, B4, WST);   // Vs
    attention(B2, B3, B4, B2, tid);
    gemm_core(p.pw_o2s, 128, p.pb_o2s, B2, nullptr, B3, WST);   // F_o2s -> B3

    // --- direction sar->opt ---
    gemm_core(p.wq_sar, 128, p.bq_sar, B1, nullptr, B2, WST);   // Qs
    gemm_core(p.wk_opt, 128, p.bk_opt, B0, nullptr, B4, WST);   // Ko
    gemm_core(p.wv_opt, 128, p.bv_opt, B0, nullptr, B0, WST);   // Vo (in-place)
    attention(B2, B4, B0, B2, tid);
    load_window(B0, p.F_opt, gbase, tid);                       // reload F_opt
    gemm_core(p.pw_s2o, 128, p.pb_s2o, B2, nullptr, B4, WST);   // F_s2o -> B4

    // --- gate opt: sigma = sigmoid(Wg @ [F_opt ; F_o2s]) ---
    gemm_core(p.gow, 256, p.gob, B0, B3, B2, WST);
    for (int idx = tid; idx < NPIX * CC; idx += TB) {
        const int off = (idx >> 7) * XP + (idx & 127);
        const float s = sigmoidf_(B2[off]);
        B2[off] = s;
        B3[off] = B0[off] + s * B3[off];       // F_opt_new
    }
    __syncthreads();
    store_window(p.out + NTOT, B2, gbase, tid);      // sigma_opt

    // --- gate sar ---
    gemm_core(p.gsw, 256, p.gsb, B1, B4, B0, WST);   // leading sync orders above
    for (int idx = tid; idx < NPIX * CC; idx += TB) {
        const int off = (idx >> 7) * XP + (idx & 127);
        const float s = sigmoidf_(B0[off]);
        B0[off] = s;
        B4[off] = B1[off] + s * B4[off];       // F_sar_new
    }
    __syncthreads();
    store_window(p.out + 2 * NTOT, B0, gbase, tid);  // sigma_sar

    // --- fuse + BN + SiLU ---
    gemm_core(p.fw, 256, p.fb, B3, B4, B2, WST);
    {
        const int c = tid;
        const float inv = p.gma[c] * rsqrtf(p.var[c] + 1e-5f);
        const float sh  = p.bta[c] - p.mu[c] * inv;
        float* g = p.out + gbase + c * (HH * WWI);
        const float* sp0 = B2 + c;
#pragma unroll
        for (int i = 0; i < 8; ++i) {
            const float* sp = sp0 + i * 8 * XP;
            float y[8];
#pragma unroll
            for (int k = 0; k < 8; ++k) {
                float v = sp[k * XP] * inv + sh;
                y[k] = v * sigmoidf_(v);
            }
            *(float4*)(g + i * WWI)     = make_float4(y[0], y[1], y[2], y[3]);
            *(float4*)(g + i * WWI + 4) = make_float4(y[4], y[5], y[6], y[7]);
        }
    }
}

extern "C" void kernel_launch(void* const* d_in, const int* in_sizes, int n_in,
                              void* d_out, int out_size) {
    (void)in_sizes; (void)n_in; (void)out_size;
    P p;
    p.F_opt  = (const float*)d_in[0];  p.F_sar  = (const float*)d_in[1];
    p.wq_opt = (const float*)d_in[2];  p.bq_opt = (const float*)d_in[3];
    p.wk_opt = (const float*)d_in[4];  p.bk_opt = (const float*)d_in[5];
    p.wv_opt = (const float*)d_in[6];  p.bv_opt = (const float*)d_in[7];
    p.wq_sar = (const float*)d_in[8];  p.bq_sar = (const float*)d_in[9];
    p.wk_sar = (const float*)d_in[10]; p.bk_sar = (const float*)d_in[11];
    p.wv_sar = (const float*)d_in[12]; p.bv_sar = (const float*)d_in[13];
    p.pw_o2s = (const float*)d_in[14]; p.pb_o2s = (const float*)d_in[15];
    p.pw_s2o = (const float*)d_in[16]; p.pb_s2o = (const float*)d_in[17];
    p.gow    = (const float*)d_in[18]; p.gob    = (const float*)d_in[19];
    p.gsw    = (const float*)d_in[20]; p.gsb    = (const float*)d_in[21];
    p.fw     = (const float*)d_in[22]; p.fb     = (const float*)d_in[23];
    p.gma    = (const float*)d_in[24]; p.bta    = (const float*)d_in[25];
    p.mu     = (const float*)d_in[26]; p.var    = (const float*)d_in[27];
    p.out    = (float*)d_out;

    const size_t smem_bytes = SMEM_FLOATS * sizeof(float);  // 203776
    cudaFuncSetAttribute(cmafm_kernel, cudaFuncAttributeMaxDynamicSharedMemorySize,
                         (int)smem_bytes);
    cmafm_kernel<<<4096, TB, smem_bytes>>>(p);
}

// round 7
// speedup vs baseline: 1.1517x; 1.1517x over previous
#include <cuda_runtime.h>
#include <cstdint>

// ---------------------------------------------------------------------------
// CMAFM block, fully fused: one CTA per 8x8 window. 4096 CTAs, 256 threads.
// GEMMs: 4x8 per-thread micro-tile, f32x2 packed FMA, weights staged in
// 32-k pieces via double-buffered cp.async. 5 rotating data buffers.
// Attention: 8 warps = 4 heads x 2 row-halves, single-pass no-max softmax
// (scores ~0.05; softmax is shift-invariant, validated rel_err 3.5e-7).
// ---------------------------------------------------------------------------

#define TB 256
using u64 = unsigned long long;

constexpr int CC    = 128;
constexpr int HH    = 256;
constexpr int WWI   = 256;
constexpr int NPIX  = 64;
constexpr int XP    = 132;          // data buffer row pitch (floats); 132 % 32 == 4
constexpr int WPI   = 36;           // weight piece pitch (floats);    36 % 32 == 4
constexpr int PIECE = 128 * WPI;    // 4608 floats (128 outch x 32 k)
constexpr int BUF   = NPIX * XP;    // 8448 floats
constexpr int SMEM_FLOATS = 5 * BUF + 2 * PIECE;  // 42240 + 9216 = 51456 (205824 B)
constexpr size_t NTOT = 4ull * 128 * 256 * 256;

struct P {
    const float *F_opt, *F_sar;
    const float *wq_opt, *bq_opt, *wk_opt, *bk_opt, *wv_opt, *bv_opt;
    const float *wq_sar, *bq_sar, *wk_sar, *bk_sar, *wv_sar, *bv_sar;
    const float *pw_o2s, *pb_o2s, *pw_s2o, *pb_s2o;
    const float *gow, *gob, *gsw, *gsb;
    const float *fw, *fb;
    const float *gma, *bta, *mu, *var;
    float *out;
};

// ---- f32x2 helpers --------------------------------------------------------
__device__ __forceinline__ void f2fma(u64& d, u64 a, u64 b) {
    asm("fma.rn.f32x2 %0, %1, %2, %0;" : "+l"(d) : "l"(a), "l"(b));
}
__device__ __forceinline__ u64 f2mul(u64 a, u64 b) {
    u64 d; asm("mul.rn.f32x2 %0, %1, %2;" : "=l"(d) : "l"(a), "l"(b)); return d;
}
__device__ __forceinline__ u64 f2add(u64 a, u64 b) {
    u64 d; asm("add.rn.f32x2 %0, %1, %2;" : "=l"(d) : "l"(a), "l"(b)); return d;
}
__device__ __forceinline__ u64 dup2(float v) {
    u64 d; asm("mov.b64 %0, {%1, %1};" : "=l"(d) : "f"(v)); return d;
}
__device__ __forceinline__ float f2sum(u64 a) {
    float lo, hi; asm("mov.b64 {%0, %1}, %2;" : "=f"(lo), "=f"(hi) : "l"(a));
    return lo + hi;
}
__device__ __forceinline__ void cp16(uint32_t s, const float* g) {
    asm volatile("cp.async.cg.shared.global [%0], [%1], 16;" :: "r"(s), "l"(g));
}

// Load one window (64 px x 128 ch) from NCHW global into smem [n][c].
__device__ __forceinline__ void load_window(float* dst, const float* __restrict__ src,
                                            int gbase, int tid) {
    const int c = tid >> 1, qq = tid & 1;
    const float* s = src + gbase + c * (HH * WWI) + qq * 4;
#pragma unroll
    for (int i = 0; i < 8; ++i) {
        float4 v = *(const float4*)(s + i * WWI);
        float* d = dst + (i * 8 + qq * 4) * XP + c;
        d[0] = v.x; d[XP] = v.y; d[2 * XP] = v.z; d[3 * XP] = v.w;
    }
}

// Transposed store: smem [n][c] -> NCHW global.
__device__ __forceinline__ void store_window(float* __restrict__ g, const float* sbuf,
                                             int gbase, int tid) {
    const int c = tid >> 1, qq = tid & 1;
    float* gp = g + gbase + c * (HH * WWI) + qq * 4;
    const float* sp0 = sbuf + qq * 4 * XP + c;
#pragma unroll
    for (int i = 0; i < 8; ++i) {
        const float* sp = sp0 + i * 8 * XP;
        *(float4*)(gp + i * WWI) = make_float4(sp[0], sp[XP], sp[2 * XP], sp[3 * XP]);
    }
}

// Stage one 32-k piece of W (128 rows x 32 cols) into wst via cp.async.
__device__ __forceinline__ void stage_piece(const float* __restrict__ Wg, int CIN,
                                            int p, float* wst, int tid) {
    const uint32_t s = (uint32_t)__cvta_generic_to_shared(wst);
    const float* Wp = Wg + p * 32;
#pragma unroll
    for (int it = 0; it < 4; ++it) {
        const int idx = tid * 4 + it * (TB * 4);
        const int r = idx >> 5, k = idx & 31;
        cp16(s + (r * WPI + k) * 4, Wp + r * CIN + k);
    }
    asm volatile("cp.async.commit_group;");
}

// ---------------------------------------------------------------------------
// out[64][128] = [x0 | x1][64][CIN] @ W^T + bias.  W row-major [128][CIN].
// 4x8 per-thread tile: rows rg+16i, cols cg+16j. k consumed in 32-wide
// pieces, double-buffered via cp.async. In-place (outb==x0) needs INPLACE.
// ---------------------------------------------------------------------------
template <bool INPLACE>
__device__ __noinline__ void gemm_core(const float* __restrict__ Wg, int CIN,
                                       const float* __restrict__ bias,
                                       const float* __restrict__ x0,
                                       const float* __restrict__ x1,
                                       float* __restrict__ outb,
                                       float* __restrict__ wst0) {
    const int tid = threadIdx.x;
    const int L = tid & 31, w = tid >> 5;
    const int rg = (L & 3) | ((w & 3) << 2);     // 0..15
    const int cg = (L >> 2) | ((w >> 2) << 3);   // 0..15
    const int np = CIN >> 5;                     // 4 or 8

    u64 acc[4][8];
#pragma unroll
    for (int i = 0; i < 4; ++i)
#pragma unroll
        for (int j = 0; j < 8; ++j) acc[i][j] = 0ull;

    stage_piece(Wg, CIN, 0, wst0, tid);

    for (int p = 0; p < np; ++p) {
        asm volatile("cp.async.wait_group 0;");
        __syncthreads();  // piece p visible to all; all readers of piece p-1 done
        if (p + 1 < np)
            stage_piece(Wg, CIN, p + 1, wst0 + ((p + 1) & 1) * PIECE, tid);

        const float* xs = ((p >= 4) ? x1 + (p - 4) * 32 : x0 + p * 32) + rg * XP;
        const float* wr = wst0 + (p & 1) * PIECE + cg * WPI;
#pragma unroll 2
        for (int ci = 0; ci < 32; ci += 4) {
            ulonglong2 xa0 = *(const ulonglong2*)(xs + ci);
            ulonglong2 xa1 = *(const ulonglong2*)(xs + 16 * XP + ci);
            ulonglong2 xa2 = *(const ulonglong2*)(xs + 32 * XP + ci);
            ulonglong2 xa3 = *(const ulonglong2*)(xs + 48 * XP + ci);
            ulonglong2 wb0 = *(const ulonglong2*)(wr + ci);
            ulonglong2 wb1 = *(const ulonglong2*)(wr + 16 * WPI + ci);
            ulonglong2 wb2 = *(const ulonglong2*)(wr + 32 * WPI + ci);
            ulonglong2 wb3 = *(const ulonglong2*)(wr + 48 * WPI + ci);
            ulonglong2 wb4 = *(const ulonglong2*)(wr + 64 * WPI + ci);
            ulonglong2 wb5 = *(const ulonglong2*)(wr + 80 * WPI + ci);
            ulonglong2 wb6 = *(const ulonglong2*)(wr + 96 * WPI + ci);
            ulonglong2 wb7 = *(const ulonglong2*)(wr + 112 * WPI + ci);
#define ROW(i, xa) \
            f2fma(acc[i][0], xa.x, wb0.x); f2fma(acc[i][0], xa.y, wb0.y); \
            f2fma(acc[i][1], xa.x, wb1.x); f2fma(acc[i][1], xa.y, wb1.y); \
            f2fma(acc[i][2], xa.x, wb2.x); f2fma(acc[i][2], xa.y, wb2.y); \
            f2fma(acc[i][3], xa.x, wb3.x); f2fma(acc[i][3], xa.y, wb3.y); \
            f2fma(acc[i][4], xa.x, wb4.x); f2fma(acc[i][4], xa.y, wb4.y); \
            f2fma(acc[i][5], xa.x, wb5.x); f2fma(acc[i][5], xa.y, wb5.y); \
            f2fma(acc[i][6], xa.x, wb6.x); f2fma(acc[i][6], xa.y, wb6.y); \
            f2fma(acc[i][7], xa.x, wb7.x); f2fma(acc[i][7], xa.y, wb7.y);
            ROW(0, xa0) ROW(1, xa1) ROW(2, xa2) ROW(3, xa3)
#undef ROW
        }
    }
    if (INPLACE) __syncthreads();  // all reads of x done before in-place writes
#pragma unroll
    for (int j = 0; j < 8; ++j) {
        const int cc = cg + 16 * j;
        const float b = __ldg(bias + cc);
#pragma unroll
        for (int i = 0; i < 4; ++i)
            outb[(rg + 16 * i) * XP + cc] = f2sum(acc[i][j]) + b;
    }
    __syncthreads();
}

// ---------------------------------------------------------------------------
// Window attention: 8 warps = 4 heads x 2 row-halves; lane owns one query
// row. head_dim=32 = 16 packed f32x2. Single pass, no-max softmax.
// Ob may alias Qb (q fully in regs before the sync).
// ---------------------------------------------------------------------------
__device__ __forceinline__ void attention(const float* __restrict__ Qb,
                                          const float* __restrict__ Kb,
                                          const float* __restrict__ Vb,
                                          float* __restrict__ Ob, int tid) {
    const int L = tid & 31, w = tid >> 5;
    const int head = w >> 1;
    const int row  = (w & 1) * 32 + L;

    u64 q[16];
    {
        const ulonglong2* qp = (const ulonglong2*)(Qb + row * XP + head * 32);
        const u64 sc2 = dup2(0.17677669529663687f);  // 32^-0.5
#pragma unroll
        for (int t = 0; t < 8; ++t) {
            ulonglong2 v = qp[t];
            q[2 * t]     = f2mul(v.x, sc2);
            q[2 * t + 1] = f2mul(v.y, sc2);
        }
    }
    __syncthreads();  // all q loaded before Ob (=Qb) is overwritten

    const float* kbase = Kb + head * 32;
    const float* vbase = Vb + head * 32;

    float l = 0.f;
    u64 o[16];
#pragma unroll
    for (int t = 0; t < 16; ++t) o[t] = 0ull;

    for (int j = 0; j < 64; ++j) {
        const ulonglong2* kp = (const ulonglong2*)(kbase + j * XP);
        u64 d0 = 0ull, d1 = 0ull, d2 = 0ull, d3 = 0ull;
#pragma unroll
        for (int t = 0; t < 4; ++t) {
            ulonglong2 ka = kp[2 * t], kb = kp[2 * t + 1];
            f2fma(d0, q[4 * t],     ka.x);
            f2fma(d1, q[4 * t + 1], ka.y);
            f2fma(d2, q[4 * t + 2], kb.x);
            f2fma(d3, q[4 * t + 3], kb.y);
        }
        const float e = __expf(f2sum(f2add(f2add(d0, d1), f2add(d2, d3))));
        l += e;
        const u64 ee = dup2(e);
        const ulonglong2* vp = (const ulonglong2*)(vbase + j * XP);
#pragma unroll
        for (int t = 0; t < 8; ++t) {
            ulonglong2 v2 = vp[t];
            f2fma(o[2 * t],     ee, v2.x);
            f2fma(o[2 * t + 1], ee, v2.y);
        }
    }
    const u64 inv2 = dup2(1.f / l);
    ulonglong2* op = (ulonglong2*)(Ob + row * XP + head * 32);
#pragma unroll
    for (int t = 0; t < 8; ++t) {
        ulonglong2 r;
        r.x = f2mul(o[2 * t], inv2);
        r.y = f2mul(o[2 * t + 1], inv2);
        op[t] = r;
    }
    __syncthreads();
}

__device__ __forceinline__ float sigmoidf_(float x) {
    return 1.f / (1.f + __expf(-x));
}

extern __shared__ float smem[];

__global__ void __launch_bounds__(TB, 1) cmafm_kernel(P p) {
    float* B0 = smem;
    float* B1 = smem + BUF;
    float* B2 = smem + 2 * BUF;
    float* B3 = smem + 3 * BUF;
    float* B4 = smem + 4 * BUF;
    float* WST = smem + 5 * BUF;

    const int tid  = threadIdx.x;
    const int widx = blockIdx.x;
    const int b  = widx >> 10;
    const int wh = (widx >> 5) & 31;
    const int ww = widx & 31;
    const int gbase = b * (CC * HH * WWI) + (wh * 8) * WWI + ww * 8;

    load_window(B0, p.F_opt, gbase, tid);
    load_window(B1, p.F_sar, gbase, tid);
    __syncthreads();

    // --- direction opt->sar ---
    gemm_core<false>(p.wq_opt, 128, p.bq_opt, B0, nullptr, B2, WST);   // Qo
    gemm_core<false>(p.wk_sar, 128, p.bk_sar, B1, nullptr, B3, WST);   // Ks
    gemm_core<false>(p.wv_sar, 128, p.bv_sar, B1, nullptr, B4, WST);   // Vs
    attention(B2, B3, B4, B2, tid);
    gemm_core<false>(p.pw_o2s, 128, p.pb_o2s, B2, nullptr, B3, WST);   // F_o2s -> B3

    // --- direction sar->opt ---
    gemm_core<false>(p.wq_sar, 128, p.bq_sar, B1, nullptr, B2, WST);   // Qs
    gemm_core<false>(p.wk_opt, 128, p.bk_opt, B0, nullptr, B4, WST);   // Ko
    gemm_core<true >(p.wv_opt, 128, p.bv_opt, B0, nullptr, B0, WST);   // Vo in-place
    attention(B2, B4, B0, B2, tid);
    load_window(B0, p.F_opt, gbase, tid);                              // reload F_opt
    gemm_core<false>(p.pw_s2o, 128, p.pb_s2o, B2, nullptr, B4, WST);   // F_s2o -> B4

    // --- gate opt: sigma = sigmoid(Wg @ [F_opt ; F_o2s]) ---
    gemm_core<false>(p.gow, 256, p.gob, B0, B3, B2, WST);
    for (int idx = tid; idx < NPIX * CC; idx += TB) {
        const int off = (idx >> 7) * XP + (idx & 127);
        const float s = sigmoidf_(B2[off]);
        B2[off] = s;
        B3[off] = B0[off] + s * B3[off];       // F_opt_new
    }
    __syncthreads();
    store_window(p.out + NTOT, B2, gbase, tid);      // sigma_opt

    // --- gate sar ---
    gemm_core<false>(p.gsw, 256, p.gsb, B1, B4, B0, WST);  // leading sync inside
    for (int idx = tid; idx < NPIX * CC; idx += TB) {
        const int off = (idx >> 7) * XP + (idx & 127);
        const float s = sigmoidf_(B0[off]);
        B0[off] = s;
        B4[off] = B1[off] + s * B4[off];       // F_sar_new
    }
    __syncthreads();
    store_window(p.out + 2 * NTOT, B0, gbase, tid);  // sigma_sar

    // --- fuse + BN + SiLU ---
    gemm_core<false>(p.fw, 256, p.fb, B3, B4, B2, WST);
    {
        const int c = tid >> 1, qq = tid & 1;
        const float inv = p.gma[c] * rsqrtf(p.var[c] + 1e-5f);
        const float sh  = p.bta[c] - p.mu[c] * inv;
        float* g = p.out + gbase + c * (HH * WWI) + qq * 4;
        const float* sp0 = B2 + qq * 4 * XP + c;
#pragma unroll
        for (int i = 0; i < 8; ++i) {
            const float* sp = sp0 + i * 8 * XP;
            float y0 = sp[0]      * inv + sh;
            float y1 = sp[XP]     * inv + sh;
            float y2 = sp[2 * XP] * inv + sh;
            float y3 = sp[3 * XP] * inv + sh;
            y0 *= sigmoidf_(y0); y1 *= sigmoidf_(y1);
            y2 *= sigmoidf_(y2); y3 *= sigmoidf_(y3);
            *(float4*)(g + i * WWI) = make_float4(y0, y1, y2, y3);
        }
    }
}

extern "C" void kernel_launch(void* const* d_in, const int* in_sizes, int n_in,
                              void* d_out, int out_size) {
    (void)in_sizes; (void)n_in; (void)out_size;
    P p;
    p.F_opt  = (const float*)d_in[0];  p.F_sar  = (const float*)d_in[1];
    p.wq_opt = (const float*)d_in[2];  p.bq_opt = (const float*)d_in[3];
    p.wk_opt = (const float*)d_in[4];  p.bk_opt = (const float*)d_in[5];
    p.wv_opt = (const float*)d_in[6];  p.bv_opt = (const float*)d_in[7];
    p.wq_sar = (const float*)d_in[8];  p.bq_sar = (const float*)d_in[9];
    p.wk_sar = (const float*)d_in[10]; p.bk_sar = (const float*)d_in[11];
    p.wv_sar = (const float*)d_in[12]; p.bv_sar = (const float*)d_in[13];
    p.pw_o2s = (const float*)d_in[14]; p.pb_o2s = (const float*)d_in[15];
    p.pw_s2o = (const float*)d_in[16]; p.pb_s2o = (const float*)d_in[17];
    p.gow    = (const float*)d_in[18]; p.gob    = (const float*)d_in[19];
    p.gsw    = (const float*)d_in[20]; p.gsb    = (const float*)d_in[21];
    p.fw     = (const float*)d_in[22]; p.fb     = (const float*)d_in[23];
    p.gma    = (const float*)d_in[24]; p.bta    = (const float*)d_in[25];
    p.mu     = (const float*)d_in[26]; p.var    = (const float*)d_in[27];
    p.out    = (float*)d_out;

    const size_t smem_bytes = SMEM_FLOATS * sizeof(float);  // 205824
    cudaFuncSetAttribute(cmafm_kernel, cudaFuncAttributeMaxDynamicSharedMemorySize,
                         (int)smem_bytes);
    cmafm_kernel<<<4096, TB, smem_bytes>>>(p);
}